// round 3
// baseline (speedup 1.0000x reference)
#include <cuda_runtime.h>

#define Bn 2048
#define NB 2000
#define DB 30
#define KK 20
#define LL 40
#define PP 2

typedef unsigned long long u64;

// Scratch (no allocations allowed in kernel_launch)
__device__ float d_wact[NB * LL];          // sigmoid((r - kappa))        [NB, L]
__device__ float d_gT[LL * Bn];            // g transposed                [L, B]
__device__ float d_partial[LL * KK * Bn];  // alpha-weighted per-(l,k)    [L, K, B]

// ---------------- packed f32x2 helpers --------------------------------------
__device__ __forceinline__ u64 pack2(float lo, float hi) {
    u64 r; asm("mov.b64 %0, {%1, %2};" : "=l"(r) : "f"(lo), "f"(hi)); return r;
}
__device__ __forceinline__ void unpack2(u64 v, float& lo, float& hi) {
    asm("mov.b64 {%0, %1}, %2;" : "=f"(lo), "=f"(hi) : "l"(v));
}
__device__ __forceinline__ u64 ffma2(u64 a, u64 b, u64 c) {
    u64 d; asm("fma.rn.f32x2 %0, %1, %2, %3;" : "=l"(d) : "l"(a), "l"(b), "l"(c)); return d;
}
__device__ __forceinline__ u64 fadd2(u64 a, u64 b) {
    u64 d; asm("add.rn.f32x2 %0, %1, %2;" : "=l"(d) : "l"(a), "l"(b)); return d;
}
__device__ __forceinline__ u64 fmul2(u64 a, u64 b) {
    u64 d; asm("mul.rn.f32x2 %0, %1, %2;" : "=l"(d) : "l"(a), "l"(b)); return d;
}
__device__ __forceinline__ float ex2(float x) {
    float r; asm("ex2.approx.f32 %0, %1;" : "=f"(r) : "f"(x)); return r;
}
// elu(z)+1 = max(z,0) + exp2(min(z,0)*log2e)   (the -1 is absorbed into the
// NEXT layer's bias: b' = b - rowsum(W))
__device__ __forceinline__ float elup1(float z) {
    return fmaxf(z, 0.f) + ex2(fminf(z, 0.f) * 1.44269504f);
}
__device__ __forceinline__ u64 elup1_2(u64 z) {
    float lo, hi; unpack2(z, lo, hi);
    return pack2(elup1(lo), elup1(hi));
}

// ---------------------------------------------------------------------------
// Kernel A: w_act[m,l] = sigmoid(r[l] - ||microbe_locs[m]-mu_bug[l]||^2)
// ---------------------------------------------------------------------------
__global__ void k_wact(const float* __restrict__ ml, const float* __restrict__ mu,
                       const float* __restrict__ r) {
    int idx = blockIdx.x * blockDim.x + threadIdx.x;
    if (idx >= NB * LL) return;
    int m = idx / LL, l = idx % LL;
    const float* a = ml + m * DB;
    const float* c = mu + l * DB;
    float s = 0.f;
#pragma unroll
    for (int d = 0; d < DB; d++) { float t = a[d] - c[d]; s = fmaf(t, t, s); }
    float z = r[l] - s;
    d_wact[idx] = 1.0f / (1.0f + __expf(-z));
}

// ---------------------------------------------------------------------------
// Kernel B: gT[l,b] = sum_m x[b,m] * w_act[m,l]
// ---------------------------------------------------------------------------
#define CH 128
#define XS (CH + 5)

__global__ __launch_bounds__(320) void k_gemm(const float* __restrict__ x) {
    __shared__ __align__(16) float xs[16 * XS];
    __shared__ __align__(16) float ws[CH * LL];
    int b0  = blockIdx.x * 16;
    int tid = threadIdx.x;
    int row = tid & 15;
    int cg  = tid >> 4;            // 0..19, 2 cols each
    float acc0 = 0.f, acc1 = 0.f;
    for (int m0 = 0; m0 < NB; m0 += CH) {
        for (int e = tid; e < 16 * CH; e += 320) {
            int rr = e >> 7, cc = e & (CH - 1);
            int m = m0 + cc;
            xs[rr * XS + cc] = (m < NB) ? x[(b0 + rr) * NB + m] : 0.f;
        }
        for (int e = tid; e < CH * LL; e += 320) {
            int m = m0 + e / LL;
            ws[e] = (m < NB) ? d_wact[m0 * LL + e] : 0.f;
        }
        __syncthreads();
#pragma unroll 4
        for (int mm = 0; mm < CH; mm++) {
            float  xv = xs[row * XS + mm];
            float2 w  = *(const float2*)&ws[mm * LL + 2 * cg];
            acc0 = fmaf(xv, w.x, acc0);
            acc1 = fmaf(xv, w.y, acc1);
        }
        __syncthreads();
    }
    d_gT[(2 * cg)     * Bn + b0 + row] = acc0;
    d_gT[(2 * cg + 1) * Bn + b0 + row] = acc1;
}

// ---------------------------------------------------------------------------
// Kernel C: NAM, packed f32x2, one pair (2 batch elems) per thread per pass.
// Weights duplicated (w,w) into smem as u64; all LDS are lane-broadcast.
// Biases of layers 2..4 are pre-adjusted by -rowsum(W) so ELU is computed as
// elu+1 (5 ops, no -1).
// partial[l,k,b] = sigmoid(alpha[l,k]) * sum_p F_{klp}(g[b,l])
// ---------------------------------------------------------------------------
__global__ __launch_bounds__(256, 2) void k_nam(
    const float* __restrict__ W1, const float* __restrict__ b1,
    const float* __restrict__ W2, const float* __restrict__ b2,
    const float* __restrict__ W3, const float* __restrict__ b3,
    const float* __restrict__ W4, const float* __restrict__ b4,
    const float* __restrict__ alpha) {
    __shared__ __align__(16) u64 sW1d[PP][16], sB1d[PP][16], sB2d[PP][16];
    __shared__ __align__(16) u64 sW2d[PP][16][16];   // [p][j][i] = dup(W2[klp,i,j])
    __shared__ __align__(16) u64 sW3d[PP][8][16];    // [p][j][i] = dup(W3[klp,i,j])
    __shared__ __align__(16) u64 sB3d[PP][8], sW4d[PP][8];
    __shared__ __align__(16) u64 sB4d[PP];

    int k = blockIdx.x / LL, l = blockIdx.x % LL;
    int tid  = threadIdx.x;
    int base = (k * LL + l) * PP;       // flat klp index of p=0

    if (tid < 32) {
        int p = tid >> 4, i = tid & 15;
        float w = W1[base * 16 + tid];  sW1d[p][i] = pack2(w, w);
        float a = b1[base * 16 + tid];  sB1d[p][i] = pack2(a, a);
        // adjusted b2': b2[j] - sum_i W2[i][j]
        float c = b2[base * 16 + tid];
        const float* w2p = W2 + base * 256 + p * 256;   // [i][j]
#pragma unroll
        for (int ii = 0; ii < 16; ii++) c -= w2p[ii * 16 + i];
        sB2d[p][i] = pack2(c, c);
    }
#pragma unroll
    for (int e = tid; e < PP * 256; e += 256) {      // W2[p][i][j] -> sW2d[p][j][i]
        int p = e >> 8, i = (e >> 4) & 15, j = e & 15;
        float w = W2[base * 256 + e];
        sW2d[p][j][i] = pack2(w, w);
    }
    if (tid < PP * 128) {                            // W3[p][i(16)][j(8)] -> sW3d[p][j][i]
        int p = tid >> 7, i = (tid >> 3) & 15, j = tid & 7;
        float w = W3[base * 128 + tid];
        sW3d[p][j][i] = pack2(w, w);
    }
    if (tid < 16) {
        int p = tid >> 3, j = tid & 7;
        // adjusted b3': b3[j] - sum_i W3[i][j]
        float a = b3[base * 8 + tid];
        const float* w3p = W3 + base * 128 + p * 128;   // [i(16)][j(8)]
#pragma unroll
        for (int ii = 0; ii < 16; ii++) a -= w3p[ii * 8 + j];
        sB3d[p][j] = pack2(a, a);
        float w = W4[base * 8 + tid];  sW4d[p][j] = pack2(w, w);
    }
    if (tid < 2) {
        // adjusted b4': b4 - sum_i W4[i]
        float a = b4[base + tid];
        const float* w4p = W4 + base * 8 + tid * 8;
#pragma unroll
        for (int ii = 0; ii < 8; ii++) a -= w4p[ii];
        sB4d[tid] = pack2(a, a);
    }
    __syncthreads();

    float aAct = 1.0f / (1.0f + __expf(-alpha[l * KK + k]));
    u64 aAct2 = pack2(aAct, aAct);
    float* outp = d_partial + (l * KK + k) * Bn;
    const float* gp = d_gT + l * Bn;

#pragma unroll 1
    for (int pass = 0; pass < 4; pass++) {
        int b0 = pass * 512 + 2 * tid;
        float2 g = *(const float2*)&gp[b0];
        u64 G = pack2(g.x, g.y);
        u64 S = 0ull;

#pragma unroll 1
        for (int p = 0; p < PP; p++) {
            u64 t1[16];                                // elu(h1)+1
#pragma unroll
            for (int i = 0; i < 16; i++)
                t1[i] = elup1_2(ffma2(G, sW1d[p][i], sB1d[p][i]));

            u64 t2[16];                                // elu(h2)+1
#pragma unroll
            for (int j = 0; j < 16; j++) {
                const ulonglong2* wr = (const ulonglong2*)sW2d[p][j];
                u64 e = sB2d[p][j], o = 0ull;
#pragma unroll
                for (int q = 0; q < 8; q++) {
                    ulonglong2 w = wr[q];
                    e = ffma2(t1[2 * q],     w.x, e);
                    o = ffma2(t1[2 * q + 1], w.y, o);
                }
                t2[j] = elup1_2(fadd2(e, o));
            }

            u64 t3[8];                                 // elu(h3)+1
#pragma unroll
            for (int j = 0; j < 8; j++) {
                const ulonglong2* wr = (const ulonglong2*)sW3d[p][j];
                u64 e = sB3d[p][j], o = 0ull;
#pragma unroll
                for (int q = 0; q < 8; q++) {
                    ulonglong2 w = wr[q];
                    e = ffma2(t2[2 * q],     w.x, e);
                    o = ffma2(t2[2 * q + 1], w.y, o);
                }
                t3[j] = elup1_2(fadd2(e, o));
            }

            {
                const ulonglong2* wr = (const ulonglong2*)sW4d[p];
                u64 e = sB4d[p], o = 0ull;
#pragma unroll
                for (int q = 0; q < 4; q++) {
                    ulonglong2 w = wr[q];
                    e = ffma2(t3[2 * q],     w.x, e);
                    o = ffma2(t3[2 * q + 1], w.y, o);
                }
                S = fadd2(S, fadd2(e, o));
            }
        }

        u64 res = fmul2(aAct2, S);
        float lo, hi;
        unpack2(res, lo, hi);
        *(float2*)&outp[b0] = make_float2(lo, hi);
    }
}

// ---------------------------------------------------------------------------
// Kernel D: out[b,k] = beta[k] + sum_l partial[l,k,b]
// ---------------------------------------------------------------------------
__global__ void k_out(const float* __restrict__ beta, float* __restrict__ out) {
    int idx = blockIdx.x * blockDim.x + threadIdx.x;
    if (idx >= KK * Bn) return;
    int k = idx >> 11;       // /2048
    int b = idx & (Bn - 1);
    float s = beta[k];
#pragma unroll
    for (int l = 0; l < LL; l++) s += d_partial[(l * KK + k) * Bn + b];
    out[b * KK + k] = s;
}

// ---------------------------------------------------------------------------
extern "C" void kernel_launch(void* const* d_in, const int* in_sizes, int n_in,
                              void* d_out, int out_size) {
    const float* x     = (const float*)d_in[0];
    const float* ml    = (const float*)d_in[1];
    const float* mu    = (const float*)d_in[2];
    const float* r     = (const float*)d_in[3];
    const float* alpha = (const float*)d_in[4];
    const float* beta  = (const float*)d_in[5];
    const float* W1    = (const float*)d_in[6];
    const float* b1    = (const float*)d_in[7];
    const float* W2    = (const float*)d_in[8];
    const float* b2    = (const float*)d_in[9];
    const float* W3    = (const float*)d_in[10];
    const float* b3    = (const float*)d_in[11];
    const float* W4    = (const float*)d_in[12];
    const float* b4    = (const float*)d_in[13];
    float* out = (float*)d_out;

    k_wact<<<(NB * LL + 255) / 256, 256>>>(ml, mu, r);
    k_gemm<<<Bn / 16, 320>>>(x);
    k_nam<<<KK * LL, 256>>>(W1, b1, W2, b2, W3, b3, W4, b4, alpha);
    k_out<<<(KK * Bn + 255) / 256, 256>>>(beta, out);
}